// round 13
// baseline (speedup 1.0000x reference)
#include <cuda_runtime.h>
#include <cstdint>

#define MDIM 8192
#define KDIM 4096
#define NDIM 12288

// ---------------- scratch ----------------
__device__ __align__(16) signed char g_q[(size_t)MDIM * KDIM];   // 32 MB int8 activations
__device__ __align__(16) signed char g_w[(size_t)NDIM * KDIM];   // 48 MB int8 weights (packed)
__device__ float g_ascale[MDIM];

// ---------------- helpers ----------------
__device__ __forceinline__ uint32_t smem_u32(const void* p) {
    uint32_t a;
    asm("{ .reg .u64 t; cvta.to.shared.u64 t, %1; cvt.u32.u64 %0, t; }" : "=r"(a) : "l"(p));
    return a;
}
__device__ __forceinline__ void cpa16(uint32_t s, const void* g) {
    asm volatile("cp.async.cg.shared.global [%0], [%1], 16;" :: "r"(s), "l"(g));
}
__device__ __forceinline__ void ldsm4(uint32_t& r0, uint32_t& r1, uint32_t& r2, uint32_t& r3,
                                      uint32_t a) {
    asm volatile("ldmatrix.sync.aligned.m8n8.x4.shared.b16 {%0,%1,%2,%3}, [%4];"
                 : "=r"(r0), "=r"(r1), "=r"(r2), "=r"(r3) : "r"(a) : "memory");
}
__device__ __forceinline__ void mma_s8(int* d, const uint32_t* a, const uint32_t* b) {
    asm volatile(
        "mma.sync.aligned.m16n8k32.row.col.s32.s8.s8.s32 "
        "{%0,%1,%2,%3}, {%4,%5,%6,%7}, {%8,%9}, {%0,%1,%2,%3};"
        : "+r"(d[0]), "+r"(d[1]), "+r"(d[2]), "+r"(d[3])
        : "r"(a[0]), "r"(a[1]), "r"(a[2]), "r"(a[3]), "r"(b[0]), "r"(b[1]));
}

// ---------------- prep: weight pack (int32->int8) + activation quant, fused ----------------
constexpr int PACK_BLOCKS = (NDIM * KDIM) / (16 * 256);   // 12288
__global__ void __launch_bounds__(256) prep(const int* __restrict__ w32,
                                            const float* __restrict__ x) {
    const int bid = blockIdx.x;
    const int t = threadIdx.x;
    if (bid < PACK_BLOCKS) {
        const size_t i = (size_t)bid * 256 + t;
        const int4* src = reinterpret_cast<const int4*>(w32) + i * 4;
        uint32_t p[4];
#pragma unroll
        for (int j = 0; j < 4; j++) {
            int4 v = src[j];
            p[j] = __byte_perm(__byte_perm(v.x, v.y, 0x0040),
                               __byte_perm(v.z, v.w, 0x0040), 0x5410);
        }
        reinterpret_cast<uint4*>(g_w)[i] = make_uint4(p[0], p[1], p[2], p[3]);
        return;
    }
    const int row = bid - PACK_BLOCKS;
    const float4* xr = reinterpret_cast<const float4*>(x + (size_t)row * KDIM);
    float4 v[4];
    float am = 0.f;
#pragma unroll
    for (int i = 0; i < 4; i++) {
        v[i] = xr[t + 256 * i];
        am = fmaxf(am, fmaxf(fmaxf(fabsf(v[i].x), fabsf(v[i].y)),
                             fmaxf(fabsf(v[i].z), fabsf(v[i].w))));
    }
#pragma unroll
    for (int o = 16; o; o >>= 1) am = fmaxf(am, __shfl_xor_sync(0xffffffffu, am, o));
    __shared__ float red[8];
    if ((t & 31) == 0) red[t >> 5] = am;
    __syncthreads();
    if (t < 32) {
        float m2 = red[t & 7];
#pragma unroll
        for (int o = 4; o; o >>= 1) m2 = fmaxf(m2, __shfl_xor_sync(0xffffffffu, m2, o));
        if (t == 0) red[0] = m2;
    }
    __syncthreads();
    const float scale = red[0] / 127.0f;
    if (t == 0) g_ascale[row] = scale;
    char4* qr = reinterpret_cast<char4*>(g_q + (size_t)row * KDIM);
#pragma unroll
    for (int i = 0; i < 4; i++) {
        float a = fminf(fmaxf(rintf(v[i].x / scale), -128.f), 127.f);
        float b = fminf(fmaxf(rintf(v[i].y / scale), -128.f), 127.f);
        float c = fminf(fmaxf(rintf(v[i].z / scale), -128.f), 127.f);
        float d = fminf(fmaxf(rintf(v[i].w / scale), -128.f), 127.f);
        qr[t + 256 * i] = make_char4((signed char)(int)a, (signed char)(int)b,
                                     (signed char)(int)c, (signed char)(int)d);
    }
}

// ---- GEMM: CTA 128x256x256, 8 warps (warp tile 64x64), 2-stage cp.async,
// ---- prefetch-after-wait; frag double-buffering; 16 barriers total.
constexpr int BM = 128, BN = 256, BK = 256;
constexpr int NTHREADS = 256;
constexpr int KITERS = KDIM / BK;            // 16
constexpr int PITCH = 272;                   // 256B data + 16B pad: conflict-free ldmatrix
constexpr uint32_t A_STAGE = BM * PITCH;     // 34816
constexpr uint32_t B_STAGE = BN * PITCH;     // 69632
constexpr uint32_t SB_OFF = 2 * A_STAGE;                      // 69632
constexpr uint32_t SMEM_TOTAL = SB_OFF + 2 * B_STAGE;         // 208896

__global__ void __launch_bounds__(NTHREADS, 1) gemm_i8(
    const float* __restrict__ wscale, const float* __restrict__ bias,
    float* __restrict__ out)
{
    extern __shared__ char smem[];
    const uint32_t sb = smem_u32(smem);
    const int t = threadIdx.x;
    const int L = t & 31;
    const int wid = t >> 5;
    const int warp_m = wid & 1;    // 2 warps over M (64 rows each)
    const int warp_n = wid >> 1;   // 4 warps over N (64 cols each)

    // ---- supertiled CTA mapping for L2 reuse ----
    constexpr int NTN = NDIM / BN;  // 48
    constexpr int GM = 8;
    const int pid = blockIdx.x;
    const int ppg = GM * NTN;
    const int gidx = pid / ppg;
    const int rem = pid - gidx * ppg;
    const int m_tile = gidx * GM + (rem % GM);
    const int n_tile = rem / GM;
    const int m0 = m_tile * BM, n0 = n_tile * BN;

    const signed char* Ab = g_q + (size_t)m0 * KDIM;
    const signed char* Bb = g_w + (size_t)n0 * KDIM;

    // A: 2048 chunks of 16B -> 8 per thread. B: 4096 chunks -> 16 per thread.
    auto load_stage = [&](int s, int kit) {
        const int k0 = kit * BK;
#pragma unroll
        for (int i = 0; i < 8; i++) {
            int ch = t + NTHREADS * i;
            int r = ch >> 4, c = ch & 15;
            cpa16(sb + s * A_STAGE + r * PITCH + c * 16,
                  Ab + (size_t)r * KDIM + k0 + c * 16);
        }
#pragma unroll
        for (int i = 0; i < 16; i++) {
            int ch = t + NTHREADS * i;
            int r = ch >> 4, c = ch & 15;
            cpa16(sb + SB_OFF + s * B_STAGE + r * PITCH + c * 16,
                  Bb + (size_t)r * KDIM + k0 + c * 16);
        }
    };

    // ---- ldmatrix lane addressing ----
    const uint32_t a_lane = (uint32_t)((warp_m * 64 + (L & 15)) * PITCH + (L >> 4) * 16);
    const uint32_t b_lane = (uint32_t)((warp_n * 64 + ((L >> 4) & 1) * 8 + (L & 7)) * PITCH +
                                       ((L >> 3) & 1) * 16);

    // double-buffered fragments
    uint32_t af[2][4][4];
    uint32_t bf[2][8][2];
    int acc[4][8][4];
#pragma unroll
    for (int mt = 0; mt < 4; mt++)
#pragma unroll
        for (int nt = 0; nt < 8; nt++)
#pragma unroll
            for (int j = 0; j < 4; j++) acc[mt][nt][j] = 0;

    auto frag_load = [&](int b, int s, int ks) {
        const uint32_t sa = sb + s * A_STAGE + a_lane + ks * 32;
        const uint32_t sbB = sb + SB_OFF + s * B_STAGE + b_lane + ks * 32;
#pragma unroll
        for (int mt = 0; mt < 4; mt++)
            ldsm4(af[b][mt][0], af[b][mt][1], af[b][mt][2], af[b][mt][3],
                  sa + mt * 16 * PITCH);
#pragma unroll
        for (int p = 0; p < 4; p++)
            ldsm4(bf[b][2 * p][0], bf[b][2 * p][1], bf[b][2 * p + 1][0], bf[b][2 * p + 1][1],
                  sbB + p * 16 * PITCH);
    };
    auto mma_all = [&](int b) {
#pragma unroll
        for (int mt = 0; mt < 4; mt++)
#pragma unroll
            for (int nt = 0; nt < 8; nt++)
                mma_s8(acc[mt][nt], af[b][mt], bf[b][nt]);
    };

    // ---- prologue: prefetch stage 0 ----
    load_stage(0, 0);
    asm volatile("cp.async.commit_group;");

    // ---- mainloop: one barrier per BK=256 (8 ks chunks) ----
    for (int it = 0; it < KITERS; it++) {
        asm volatile("cp.async.wait_group 0;" ::: "memory");
        __syncthreads();
        const int s = it & 1;
        if (it + 1 < KITERS) load_stage((it + 1) & 1, it + 1);
        asm volatile("cp.async.commit_group;");
        frag_load(0, s, 0);
        frag_load(1, s, 1);
        mma_all(0);
        frag_load(0, s, 2);
        mma_all(1);
        frag_load(1, s, 3);
        mma_all(0);
        frag_load(0, s, 4);
        mma_all(1);
        frag_load(1, s, 5);
        mma_all(0);
        frag_load(0, s, 6);
        mma_all(1);
        frag_load(1, s, 7);
        mma_all(0);
        mma_all(1);
    }

    // ---- fused dequant epilogue ----
    const int g = L >> 2, q = L & 3;
    const int mbase = m0 + warp_m * 64;
    const int nbase = n0 + warp_n * 64;
#pragma unroll
    for (int mt = 0; mt < 4; mt++) {
        const int r0 = mbase + mt * 16 + g;
        const float asc0 = g_ascale[r0];
        const float asc1 = g_ascale[r0 + 8];
        float* o0 = out + (size_t)r0 * NDIM;
        float* o1 = out + (size_t)(r0 + 8) * NDIM;
#pragma unroll
        for (int nt = 0; nt < 8; nt++) {
            const int n = nbase + nt * 8 + 2 * q;
            const float2 ws = __ldg((const float2*)(wscale + n));
            const float2 bi = __ldg((const float2*)(bias + n));
            float2 v0, v1;
            v0.x = fmaf((float)acc[mt][nt][0] * asc0, ws.x, bi.x);
            v0.y = fmaf((float)acc[mt][nt][1] * asc0, ws.y, bi.y);
            v1.x = fmaf((float)acc[mt][nt][2] * asc1, ws.x, bi.x);
            v1.y = fmaf((float)acc[mt][nt][3] * asc1, ws.y, bi.y);
            *(float2*)(o0 + n) = v0;
            *(float2*)(o1 + n) = v1;
        }
    }
}

// ---------------- launch ----------------
extern "C" void kernel_launch(void* const* d_in, const int* in_sizes, int n_in,
                              void* d_out, int out_size) {
    (void)in_sizes; (void)n_in; (void)out_size;
    const float* x = (const float*)d_in[0];
    const int* w32 = (const int*)d_in[1];      // int8 weights promoted to int32 by harness
    const float* wsc = (const float*)d_in[2];
    const float* bi = (const float*)d_in[3];
    float* out = (float*)d_out;

    prep<<<PACK_BLOCKS + MDIM, 256>>>(w32, x);

    cudaFuncSetAttribute(gemm_i8, cudaFuncAttributeMaxDynamicSharedMemorySize, SMEM_TOTAL);
    gemm_i8<<<(MDIM / BM) * (NDIM / BN), NTHREADS, SMEM_TOTAL>>>(wsc, bi, out);
}

// round 15
// speedup vs baseline: 1.2749x; 1.2749x over previous
#include <cuda_runtime.h>
#include <cstdint>

#define MDIM 8192
#define KDIM 4096
#define NDIM 12288

// ---------------- scratch ----------------
__device__ __align__(16) signed char g_q[(size_t)MDIM * KDIM];   // 32 MB int8 activations
__device__ __align__(16) signed char g_w[(size_t)NDIM * KDIM];   // 48 MB int8 weights (packed)
__device__ float g_ascale[MDIM];

// ---------------- helpers ----------------
__device__ __forceinline__ uint32_t smem_u32(const void* p) {
    uint32_t a;
    asm("{ .reg .u64 t; cvta.to.shared.u64 t, %1; cvt.u32.u64 %0, t; }" : "=r"(a) : "l"(p));
    return a;
}
__device__ __forceinline__ void cpa16(uint32_t s, const void* g) {
    asm volatile("cp.async.cg.shared.global [%0], [%1], 16;" :: "r"(s), "l"(g));
}
__device__ __forceinline__ void ldsm4(uint32_t& r0, uint32_t& r1, uint32_t& r2, uint32_t& r3,
                                      uint32_t a) {
    asm volatile("ldmatrix.sync.aligned.m8n8.x4.shared.b16 {%0,%1,%2,%3}, [%4];"
                 : "=r"(r0), "=r"(r1), "=r"(r2), "=r"(r3) : "r"(a) : "memory");
}
__device__ __forceinline__ void mma_s8(int* d, const uint32_t* a, const uint32_t* b) {
    asm volatile(
        "mma.sync.aligned.m16n8k32.row.col.s32.s8.s8.s32 "
        "{%0,%1,%2,%3}, {%4,%5,%6,%7}, {%8,%9}, {%0,%1,%2,%3};"
        : "+r"(d[0]), "+r"(d[1]), "+r"(d[2]), "+r"(d[3])
        : "r"(a[0]), "r"(a[1]), "r"(a[2]), "r"(a[3]), "r"(b[0]), "r"(b[1]));
}

// ---------------- prep: weight pack (int32->int8) + activation quant, fused ----------------
constexpr int PACK_BLOCKS = (NDIM * KDIM) / (16 * 256);   // 12288
__global__ void __launch_bounds__(256) prep(const int* __restrict__ w32,
                                            const float* __restrict__ x) {
    const int bid = blockIdx.x;
    const int t = threadIdx.x;
    if (bid < PACK_BLOCKS) {
        const size_t i = (size_t)bid * 256 + t;
        const int4* src = reinterpret_cast<const int4*>(w32) + i * 4;
        uint32_t p[4];
#pragma unroll
        for (int j = 0; j < 4; j++) {
            int4 v = src[j];
            p[j] = __byte_perm(__byte_perm(v.x, v.y, 0x0040),
                               __byte_perm(v.z, v.w, 0x0040), 0x5410);
        }
        reinterpret_cast<uint4*>(g_w)[i] = make_uint4(p[0], p[1], p[2], p[3]);
        return;
    }
    const int row = bid - PACK_BLOCKS;
    const float4* xr = reinterpret_cast<const float4*>(x + (size_t)row * KDIM);
    float4 v[4];
    float am = 0.f;
#pragma unroll
    for (int i = 0; i < 4; i++) {
        v[i] = xr[t + 256 * i];
        am = fmaxf(am, fmaxf(fmaxf(fabsf(v[i].x), fabsf(v[i].y)),
                             fmaxf(fabsf(v[i].z), fabsf(v[i].w))));
    }
#pragma unroll
    for (int o = 16; o; o >>= 1) am = fmaxf(am, __shfl_xor_sync(0xffffffffu, am, o));
    __shared__ float red[8];
    if ((t & 31) == 0) red[t >> 5] = am;
    __syncthreads();
    if (t < 32) {
        float m2 = red[t & 7];
#pragma unroll
        for (int o = 4; o; o >>= 1) m2 = fmaxf(m2, __shfl_xor_sync(0xffffffffu, m2, o));
        if (t == 0) red[0] = m2;
    }
    __syncthreads();
    const float scale = red[0] / 127.0f;
    if (t == 0) g_ascale[row] = scale;
    char4* qr = reinterpret_cast<char4*>(g_q + (size_t)row * KDIM);
#pragma unroll
    for (int i = 0; i < 4; i++) {
        float a = fminf(fmaxf(rintf(v[i].x / scale), -128.f), 127.f);
        float b = fminf(fmaxf(rintf(v[i].y / scale), -128.f), 127.f);
        float c = fminf(fmaxf(rintf(v[i].z / scale), -128.f), 127.f);
        float d = fminf(fmaxf(rintf(v[i].w / scale), -128.f), 127.f);
        qr[t + 256 * i] = make_char4((signed char)(int)a, (signed char)(int)b,
                                     (signed char)(int)c, (signed char)(int)d);
    }
}

// ---- GEMM: CTA 128x128x128, 4 warps (warp tile 64x64), 3-stage cp.async,
// ---- 2 CTAs/SM so barrier stalls of one CTA are hidden by the other.
constexpr int BM = 128, BN = 128, BK = 128;
constexpr int NTHREADS = 128;
constexpr int STAGES = 3;
constexpr int KITERS = KDIM / BK;            // 32
constexpr int PITCH = 144;                   // 128B data + 16B pad: conflict-free ldmatrix
constexpr uint32_t A_STAGE = BM * PITCH;     // 18432
constexpr uint32_t B_STAGE = BN * PITCH;     // 18432
constexpr uint32_t SB_OFF = STAGES * A_STAGE;                 // 55296
constexpr uint32_t SMEM_TOTAL = SB_OFF + STAGES * B_STAGE;    // 110592  (2 CTAs/SM)

__global__ void __launch_bounds__(NTHREADS, 2) gemm_i8(
    const float* __restrict__ wscale, const float* __restrict__ bias,
    float* __restrict__ out)
{
    extern __shared__ char smem[];
    const uint32_t sb = smem_u32(smem);
    const int t = threadIdx.x;
    const int L = t & 31;
    const int wid = t >> 5;
    const int warp_m = wid & 1;    // 2 warps over M (64 rows each)
    const int warp_n = wid >> 1;   // 2 warps over N (64 cols each)

    // ---- supertiled CTA mapping for L2 reuse ----
    constexpr int NTN = NDIM / BN;  // 96
    constexpr int GM = 8;
    const int pid = blockIdx.x;
    const int ppg = GM * NTN;
    const int gidx = pid / ppg;
    const int rem = pid - gidx * ppg;
    const int m_tile = gidx * GM + (rem % GM);
    const int n_tile = rem / GM;
    const int m0 = m_tile * BM, n0 = n_tile * BN;

    const signed char* Ab = g_q + (size_t)m0 * KDIM;
    const signed char* Bb = g_w + (size_t)n0 * KDIM;

    // A: 1024 chunks of 16B -> 8 per thread. B: same.
    auto load_stage = [&](int s, int kit) {
        const int k0 = kit * BK;
#pragma unroll
        for (int i = 0; i < 8; i++) {
            int ch = t + NTHREADS * i;
            int r = ch >> 3, c = ch & 7;
            cpa16(sb + s * A_STAGE + r * PITCH + c * 16,
                  Ab + (size_t)r * KDIM + k0 + c * 16);
        }
#pragma unroll
        for (int i = 0; i < 8; i++) {
            int ch = t + NTHREADS * i;
            int r = ch >> 3, c = ch & 7;
            cpa16(sb + SB_OFF + s * B_STAGE + r * PITCH + c * 16,
                  Bb + (size_t)r * KDIM + k0 + c * 16);
        }
    };

    // ---- ldmatrix lane addressing ----
    const uint32_t a_lane = (uint32_t)((warp_m * 64 + (L & 15)) * PITCH + (L >> 4) * 16);
    const uint32_t b_lane = (uint32_t)((warp_n * 64 + ((L >> 4) & 1) * 8 + (L & 7)) * PITCH +
                                       ((L >> 3) & 1) * 16);

    // double-buffered fragments
    uint32_t af[2][4][4];
    uint32_t bf[2][8][2];
    int acc[4][8][4];
#pragma unroll
    for (int mt = 0; mt < 4; mt++)
#pragma unroll
        for (int nt = 0; nt < 8; nt++)
#pragma unroll
            for (int j = 0; j < 4; j++) acc[mt][nt][j] = 0;

    auto frag_load = [&](int b, int s, int ks) {
        const uint32_t sa = sb + s * A_STAGE + a_lane + ks * 32;
        const uint32_t sbB = sb + SB_OFF + s * B_STAGE + b_lane + ks * 32;
#pragma unroll
        for (int mt = 0; mt < 4; mt++)
            ldsm4(af[b][mt][0], af[b][mt][1], af[b][mt][2], af[b][mt][3],
                  sa + mt * 16 * PITCH);
#pragma unroll
        for (int p = 0; p < 4; p++)
            ldsm4(bf[b][2 * p][0], bf[b][2 * p][1], bf[b][2 * p + 1][0], bf[b][2 * p + 1][1],
                  sbB + p * 16 * PITCH);
    };
    auto mma_all = [&](int b) {
#pragma unroll
        for (int mt = 0; mt < 4; mt++)
#pragma unroll
            for (int nt = 0; nt < 8; nt++)
                mma_s8(acc[mt][nt], af[b][mt], bf[b][nt]);
    };

    // ---- prologue: prefetch 2 stages, load first fragment set ----
#pragma unroll
    for (int i = 0; i < STAGES - 1; i++) {
        load_stage(i, i);
        asm volatile("cp.async.commit_group;");
    }
    asm volatile("cp.async.wait_group %0;" :: "n"(STAGES - 2));
    __syncthreads();
    frag_load(0, 0, 0);

    // ---- mainloop: 4 ks chunks per barrier, frag loads overlapped with MMA ----
    int s = 0;                 // current stage
    int ps = STAGES - 1;       // prefetch stage = (it + STAGES-1) % STAGES
    for (int it = 0; it < KITERS; it++) {
        frag_load(1, s, 1);
        if (it + STAGES - 1 < KITERS) load_stage(ps, it + STAGES - 1);
        asm volatile("cp.async.commit_group;");
        mma_all(0);
        frag_load(0, s, 2);
        mma_all(1);
        frag_load(1, s, 3);
        mma_all(0);
        const int sn = (s + 1 == STAGES) ? 0 : s + 1;
        if (it + 1 < KITERS) {
            asm volatile("cp.async.wait_group %0;" :: "n"(STAGES - 2));
            __syncthreads();
            frag_load(0, sn, 0);
        }
        mma_all(1);
        s = sn;
        ps = (ps + 1 == STAGES) ? 0 : ps + 1;
    }

    // ---- fused dequant epilogue ----
    const int g = L >> 2, q = L & 3;
    const int mbase = m0 + warp_m * 64;
    const int nbase = n0 + warp_n * 64;
#pragma unroll
    for (int mt = 0; mt < 4; mt++) {
        const int r0 = mbase + mt * 16 + g;
        const float asc0 = g_ascale[r0];
        const float asc1 = g_ascale[r0 + 8];
        float* o0 = out + (size_t)r0 * NDIM;
        float* o1 = out + (size_t)(r0 + 8) * NDIM;
#pragma unroll
        for (int nt = 0; nt < 8; nt++) {
            const int n = nbase + nt * 8 + 2 * q;
            const float2 ws = __ldg((const float2*)(wscale + n));
            const float2 bi = __ldg((const float2*)(bias + n));
            float2 v0, v1;
            v0.x = fmaf((float)acc[mt][nt][0] * asc0, ws.x, bi.x);
            v0.y = fmaf((float)acc[mt][nt][1] * asc0, ws.y, bi.y);
            v1.x = fmaf((float)acc[mt][nt][2] * asc1, ws.x, bi.x);
            v1.y = fmaf((float)acc[mt][nt][3] * asc1, ws.y, bi.y);
            *(float2*)(o0 + n) = v0;
            *(float2*)(o1 + n) = v1;
        }
    }
}

// ---------------- launch ----------------
extern "C" void kernel_launch(void* const* d_in, const int* in_sizes, int n_in,
                              void* d_out, int out_size) {
    (void)in_sizes; (void)n_in; (void)out_size;
    const float* x = (const float*)d_in[0];
    const int* w32 = (const int*)d_in[1];      // int8 weights promoted to int32 by harness
    const float* wsc = (const float*)d_in[2];
    const float* bi = (const float*)d_in[3];
    float* out = (float*)d_out;

    prep<<<PACK_BLOCKS + MDIM, 256>>>(w32, x);

    cudaFuncSetAttribute(gemm_i8, cudaFuncAttributeMaxDynamicSharedMemorySize, SMEM_TOTAL);
    gemm_i8<<<(MDIM / BM) * (NDIM / BN), NTHREADS, SMEM_TOTAL>>>(wsc, bi, out);
}

// round 16
// speedup vs baseline: 1.3404x; 1.0514x over previous
#include <cuda_runtime.h>
#include <cstdint>

#define MDIM 8192
#define KDIM 4096
#define NDIM 12288

// ---------------- scratch ----------------
__device__ __align__(16) signed char g_q[(size_t)MDIM * KDIM];   // 32 MB int8 activations
__device__ __align__(16) signed char g_w[(size_t)NDIM * KDIM];   // 48 MB int8 weights (packed)
__device__ float g_ascale[MDIM];

// ---------------- helpers ----------------
__device__ __forceinline__ uint32_t smem_u32(const void* p) {
    uint32_t a;
    asm("{ .reg .u64 t; cvta.to.shared.u64 t, %1; cvt.u32.u64 %0, t; }" : "=r"(a) : "l"(p));
    return a;
}
__device__ __forceinline__ void cpa16(uint32_t s, const void* g) {
    asm volatile("cp.async.cg.shared.global [%0], [%1], 16;" :: "r"(s), "l"(g));
}
__device__ __forceinline__ void ldsm4(uint32_t& r0, uint32_t& r1, uint32_t& r2, uint32_t& r3,
                                      uint32_t a) {
    asm volatile("ldmatrix.sync.aligned.m8n8.x4.shared.b16 {%0,%1,%2,%3}, [%4];"
                 : "=r"(r0), "=r"(r1), "=r"(r2), "=r"(r3) : "r"(a) : "memory");
}
__device__ __forceinline__ void mma_s8(int* d, const uint32_t* a, const uint32_t* b) {
    asm volatile(
        "mma.sync.aligned.m16n8k32.row.col.s32.s8.s8.s32 "
        "{%0,%1,%2,%3}, {%4,%5,%6,%7}, {%8,%9}, {%0,%1,%2,%3};"
        : "+r"(d[0]), "+r"(d[1]), "+r"(d[2]), "+r"(d[3])
        : "r"(a[0]), "r"(a[1]), "r"(a[2]), "r"(a[3]), "r"(b[0]), "r"(b[1]));
}

// ---------------- prep: weight pack (int32->int8) + activation quant, fused ----------------
constexpr int PACK_BLOCKS = (NDIM * KDIM) / (16 * 256);   // 12288
__global__ void __launch_bounds__(256) prep(const int* __restrict__ w32,
                                            const float* __restrict__ x) {
    const int bid = blockIdx.x;
    const int t = threadIdx.x;
    if (bid < PACK_BLOCKS) {
        const size_t i = (size_t)bid * 256 + t;
        const int4* src = reinterpret_cast<const int4*>(w32) + i * 4;
        uint32_t p[4];
#pragma unroll
        for (int j = 0; j < 4; j++) {
            int4 v = src[j];
            p[j] = __byte_perm(__byte_perm(v.x, v.y, 0x0040),
                               __byte_perm(v.z, v.w, 0x0040), 0x5410);
        }
        reinterpret_cast<uint4*>(g_w)[i] = make_uint4(p[0], p[1], p[2], p[3]);
        return;
    }
    const int row = bid - PACK_BLOCKS;
    const float4* xr = reinterpret_cast<const float4*>(x + (size_t)row * KDIM);
    float4 v[4];
    float am = 0.f;
#pragma unroll
    for (int i = 0; i < 4; i++) {
        v[i] = xr[t + 256 * i];
        am = fmaxf(am, fmaxf(fmaxf(fabsf(v[i].x), fabsf(v[i].y)),
                             fmaxf(fabsf(v[i].z), fabsf(v[i].w))));
    }
#pragma unroll
    for (int o = 16; o; o >>= 1) am = fmaxf(am, __shfl_xor_sync(0xffffffffu, am, o));
    __shared__ float red[8];
    if ((t & 31) == 0) red[t >> 5] = am;
    __syncthreads();
    if (t < 32) {
        float m2 = red[t & 7];
#pragma unroll
        for (int o = 4; o; o >>= 1) m2 = fmaxf(m2, __shfl_xor_sync(0xffffffffu, m2, o));
        if (t == 0) red[0] = m2;
    }
    __syncthreads();
    const float scale = red[0] / 127.0f;
    if (t == 0) g_ascale[row] = scale;
    char4* qr = reinterpret_cast<char4*>(g_q + (size_t)row * KDIM);
#pragma unroll
    for (int i = 0; i < 4; i++) {
        float a = fminf(fmaxf(rintf(v[i].x / scale), -128.f), 127.f);
        float b = fminf(fmaxf(rintf(v[i].y / scale), -128.f), 127.f);
        float c = fminf(fmaxf(rintf(v[i].z / scale), -128.f), 127.f);
        float d = fminf(fmaxf(rintf(v[i].w / scale), -128.f), 127.f);
        qr[t + 256 * i] = make_char4((signed char)(int)a, (signed char)(int)b,
                                     (signed char)(int)c, (signed char)(int)d);
    }
}

// ---- GEMM: CTA 128x128x128, 4 warps (warp tile 64x64), 3-stage cp.async,
// ---- 2 CTAs/SM; cp.async quarters interleaved between MMA bursts.
constexpr int BM = 128, BN = 128, BK = 128;
constexpr int NTHREADS = 128;
constexpr int STAGES = 3;
constexpr int KITERS = KDIM / BK;            // 32
constexpr int PITCH = 144;                   // 128B data + 16B pad: conflict-free ldmatrix
constexpr uint32_t A_STAGE = BM * PITCH;     // 18432
constexpr uint32_t B_STAGE = BN * PITCH;     // 18432
constexpr uint32_t SB_OFF = STAGES * A_STAGE;                 // 55296
constexpr uint32_t SMEM_TOTAL = SB_OFF + STAGES * B_STAGE;    // 110592  (2 CTAs/SM)

__global__ void __launch_bounds__(NTHREADS, 2) gemm_i8(
    const float* __restrict__ wscale, const float* __restrict__ bias,
    float* __restrict__ out)
{
    extern __shared__ char smem[];
    const uint32_t sb = smem_u32(smem);
    const int t = threadIdx.x;
    const int L = t & 31;
    const int wid = t >> 5;
    const int warp_m = wid & 1;    // 2 warps over M (64 rows each)
    const int warp_n = wid >> 1;   // 2 warps over N (64 cols each)

    // ---- supertiled CTA mapping for L2 reuse ----
    constexpr int NTN = NDIM / BN;  // 96
    constexpr int GM = 8;
    const int pid = blockIdx.x;
    const int ppg = GM * NTN;
    const int gidx = pid / ppg;
    const int rem = pid - gidx * ppg;
    const int m_tile = gidx * GM + (rem % GM);
    const int n_tile = rem / GM;
    const int m0 = m_tile * BM, n0 = n_tile * BN;

    const signed char* Ab = g_q + (size_t)m0 * KDIM;
    const signed char* Bb = g_w + (size_t)n0 * KDIM;

    // A: 1024 chunks of 16B -> 8 per thread; B same. Quarter p = chunks {2p, 2p+1}.
    auto load_quarter = [&](int s, int kit, int p) {
        const int k0 = kit * BK;
#pragma unroll
        for (int i = 2 * p; i < 2 * p + 2; i++) {
            int ch = t + NTHREADS * i;
            int r = ch >> 3, c = ch & 7;
            cpa16(sb + s * A_STAGE + r * PITCH + c * 16,
                  Ab + (size_t)r * KDIM + k0 + c * 16);
        }
#pragma unroll
        for (int i = 2 * p; i < 2 * p + 2; i++) {
            int ch = t + NTHREADS * i;
            int r = ch >> 3, c = ch & 7;
            cpa16(sb + SB_OFF + s * B_STAGE + r * PITCH + c * 16,
                  Bb + (size_t)r * KDIM + k0 + c * 16);
        }
    };
    auto load_stage = [&](int s, int kit) {
#pragma unroll
        for (int p = 0; p < 4; p++) load_quarter(s, kit, p);
    };

    // ---- ldmatrix lane addressing ----
    const uint32_t a_lane = (uint32_t)((warp_m * 64 + (L & 15)) * PITCH + (L >> 4) * 16);
    const uint32_t b_lane = (uint32_t)((warp_n * 64 + ((L >> 4) & 1) * 8 + (L & 7)) * PITCH +
                                       ((L >> 3) & 1) * 16);

    // double-buffered fragments
    uint32_t af[2][4][4];
    uint32_t bf[2][8][2];
    int acc[4][8][4];
#pragma unroll
    for (int mt = 0; mt < 4; mt++)
#pragma unroll
        for (int nt = 0; nt < 8; nt++)
#pragma unroll
            for (int j = 0; j < 4; j++) acc[mt][nt][j] = 0;

    auto frag_load = [&](int b, int s, int ks) {
        const uint32_t sa = sb + s * A_STAGE + a_lane + ks * 32;
        const uint32_t sbB = sb + SB_OFF + s * B_STAGE + b_lane + ks * 32;
#pragma unroll
        for (int mt = 0; mt < 4; mt++)
            ldsm4(af[b][mt][0], af[b][mt][1], af[b][mt][2], af[b][mt][3],
                  sa + mt * 16 * PITCH);
#pragma unroll
        for (int p = 0; p < 4; p++)
            ldsm4(bf[b][2 * p][0], bf[b][2 * p][1], bf[b][2 * p + 1][0], bf[b][2 * p + 1][1],
                  sbB + p * 16 * PITCH);
    };
    auto mma_all = [&](int b) {
#pragma unroll
        for (int mt = 0; mt < 4; mt++)
#pragma unroll
            for (int nt = 0; nt < 8; nt++)
                mma_s8(acc[mt][nt], af[b][mt], bf[b][nt]);
    };

    // ---- prologue: prefetch 2 stages, load first fragment set ----
#pragma unroll
    for (int i = 0; i < STAGES - 1; i++) {
        load_stage(i, i);
        asm volatile("cp.async.commit_group;");
    }
    asm volatile("cp.async.wait_group %0;" :: "n"(STAGES - 2));
    __syncthreads();
    frag_load(0, 0, 0);

    // ---- mainloop: cp.async quarters spread between MMA bursts ----
    int s = 0;                 // current stage
    int ps = STAGES - 1;       // prefetch stage = (it + STAGES-1) % STAGES
    for (int it = 0; it < KITERS; it++) {
        const bool pfv = (it + STAGES - 1) < KITERS;
        const int pk = it + STAGES - 1;
        frag_load(1, s, 1);
        if (pfv) load_quarter(ps, pk, 0);
        mma_all(0);
        if (pfv) load_quarter(ps, pk, 1);
        frag_load(0, s, 2);
        mma_all(1);
        if (pfv) load_quarter(ps, pk, 2);
        frag_load(1, s, 3);
        mma_all(0);
        if (pfv) load_quarter(ps, pk, 3);
        asm volatile("cp.async.commit_group;");
        const int sn = (s + 1 == STAGES) ? 0 : s + 1;
        if (it + 1 < KITERS) {
            asm volatile("cp.async.wait_group %0;" :: "n"(STAGES - 2));
            __syncthreads();
            frag_load(0, sn, 0);
        }
        mma_all(1);
        s = sn;
        ps = (ps + 1 == STAGES) ? 0 : ps + 1;
    }

    // ---- fused dequant epilogue ----
    const int g = L >> 2, q = L & 3;
    const int mbase = m0 + warp_m * 64;
    const int nbase = n0 + warp_n * 64;
#pragma unroll
    for (int mt = 0; mt < 4; mt++) {
        const int r0 = mbase + mt * 16 + g;
        const float asc0 = g_ascale[r0];
        const float asc1 = g_ascale[r0 + 8];
        float* o0 = out + (size_t)r0 * NDIM;
        float* o1 = out + (size_t)(r0 + 8) * NDIM;
#pragma unroll
        for (int nt = 0; nt < 8; nt++) {
            const int n = nbase + nt * 8 + 2 * q;
            const float2 ws = __ldg((const float2*)(wscale + n));
            const float2 bi = __ldg((const float2*)(bias + n));
            float2 v0, v1;
            v0.x = fmaf((float)acc[mt][nt][0] * asc0, ws.x, bi.x);
            v0.y = fmaf((float)acc[mt][nt][1] * asc0, ws.y, bi.y);
            v1.x = fmaf((float)acc[mt][nt][2] * asc1, ws.x, bi.x);
            v1.y = fmaf((float)acc[mt][nt][3] * asc1, ws.y, bi.y);
            *(float2*)(o0 + n) = v0;
            *(float2*)(o1 + n) = v1;
        }
    }
}

// ---------------- launch ----------------
extern "C" void kernel_launch(void* const* d_in, const int* in_sizes, int n_in,
                              void* d_out, int out_size) {
    (void)in_sizes; (void)n_in; (void)out_size;
    const float* x = (const float*)d_in[0];
    const int* w32 = (const int*)d_in[1];      // int8 weights promoted to int32 by harness
    const float* wsc = (const float*)d_in[2];
    const float* bi = (const float*)d_in[3];
    float* out = (float*)d_out;

    prep<<<PACK_BLOCKS + MDIM, 256>>>(w32, x);

    cudaFuncSetAttribute(gemm_i8, cudaFuncAttributeMaxDynamicSharedMemorySize, SMEM_TOTAL);
    gemm_i8<<<(MDIM / BM) * (NDIM / BN), NTHREADS, SMEM_TOTAL>>>(wsc, bi, out);
}